// round 2
// baseline (speedup 1.0000x reference)
#include <cuda_runtime.h>

// NCELoss: N=4096 examples, E=1024 embed, K=50 noise samples (+1 target).
// Inputs (metadata order):
//   d_in[0] input  f32 [N,E]
//   d_in[1] target i32 [N]
//   d_in[2] noise_samples i32 [N,K]
//   d_in[3] noise  f32 [V]
//   d_in[4] weight f32 [V,E]
//   d_in[5] bias   f32 [V]
// Output: scalar f32 loss.
//
// Single fused kernel: each block computes one example's partial loss, writes
// it to a __device__ partial array, and the last block to finish reduces all
// partials (in double, fixed order) and writes the scalar. The completion
// ticket self-resets so the kernel is graph-replayable.

#define EDIM 1024
#define KNOISE 50
#define NORM_TERM 9.0f
#define NWARPS 8
#define MAXN 8192

__device__ double        g_partial[MAXN];
__device__ unsigned int  g_done = 0;

__device__ __forceinline__ float loss_term(int j, int idx, float s,
                                           const float* __restrict__ bias,
                                           const float* __restrict__ noise)
{
    const float logit = s + __ldg(&bias[idx]);
    const float p  = expf(logit - NORM_TERM);
    const float kp = (float)KNOISE * __ldg(&noise[idx]);
    const float num = (j == 0) ? p : kp;   // j==0: data term, else noise term
    return logf(num / (p + kp));
}

__global__ __launch_bounds__(NWARPS * 32) void nce_loss_kernel(
    const float* __restrict__ input,
    const int*   __restrict__ target,
    const int*   __restrict__ noise_samples,
    const float* __restrict__ noise,
    const float* __restrict__ weight,
    const float* __restrict__ bias,
    float*       __restrict__ out,
    int N)
{
    __shared__ float4 s_in[EDIM / 4];      // 4 KB: this example's input row
    __shared__ float  s_wsum[NWARPS];
    __shared__ bool   s_is_last;

    const int n    = blockIdx.x;
    const int tid  = threadIdx.x;
    const int lane = tid & 31;
    const int wid  = tid >> 5;

    // Stage input row into smem (vectorized, coalesced).
    const float4* in4 = reinterpret_cast<const float4*>(input + (size_t)n * EDIM);
    #pragma unroll
    for (int i = tid; i < EDIM / 4; i += NWARPS * 32) s_in[i] = in4[i];
    __syncthreads();

    // Each warp handles columns j = wid, wid+8, ... over [0, K+1).
    // Two columns per iteration -> 16 LDG.128 in flight per warp.
    float acc = 0.0f;
    int j = wid;
    for (; j + NWARPS < KNOISE + 1; j += 2 * NWARPS) {
        const int jb = j + NWARPS;                 // jb >= 8, always a noise col
        const int idxA = (j == 0) ? __ldg(&target[n])
                                  : __ldg(&noise_samples[n * KNOISE + (j - 1)]);
        const int idxB = __ldg(&noise_samples[n * KNOISE + (jb - 1)]);
        const float4* wA4 = reinterpret_cast<const float4*>(weight + (size_t)idxA * EDIM);
        const float4* wB4 = reinterpret_cast<const float4*>(weight + (size_t)idxB * EDIM);

        float4 wA[8], wB[8];
        #pragma unroll
        for (int i = 0; i < 8; i++) wA[i] = __ldg(&wA4[lane + 32 * i]);
        #pragma unroll
        for (int i = 0; i < 8; i++) wB[i] = __ldg(&wB4[lane + 32 * i]);

        float sA = 0.0f, sB = 0.0f;
        #pragma unroll
        for (int i = 0; i < 8; i++) {
            const float4 x = s_in[lane + 32 * i];
            sA += wA[i].x * x.x + wA[i].y * x.y + wA[i].z * x.z + wA[i].w * x.w;
            sB += wB[i].x * x.x + wB[i].y * x.y + wB[i].z * x.z + wB[i].w * x.w;
        }
        #pragma unroll
        for (int o = 16; o; o >>= 1) {
            sA += __shfl_xor_sync(0xffffffffu, sA, o);
            sB += __shfl_xor_sync(0xffffffffu, sB, o);
        }
        if (lane == 0) {
            acc += loss_term(j,  idxA, sA, bias, noise);
            acc += loss_term(jb, idxB, sB, bias, noise);
        }
    }
    if (j < KNOISE + 1) {                          // tail column
        const int idx = (j == 0) ? __ldg(&target[n])
                                 : __ldg(&noise_samples[n * KNOISE + (j - 1)]);
        const float4* w4 = reinterpret_cast<const float4*>(weight + (size_t)idx * EDIM);
        float s = 0.0f;
        #pragma unroll
        for (int i = 0; i < 8; i++) {
            const float4 w = __ldg(&w4[lane + 32 * i]);
            const float4 x = s_in[lane + 32 * i];
            s += w.x * x.x + w.y * x.y + w.z * x.z + w.w * x.w;
        }
        #pragma unroll
        for (int o = 16; o; o >>= 1) s += __shfl_xor_sync(0xffffffffu, s, o);
        if (lane == 0) acc += loss_term(j, idx, s, bias, noise);
    }

    if (lane == 0) s_wsum[wid] = acc;
    __syncthreads();

    if (wid == 0) {
        float v = (lane < NWARPS) ? s_wsum[lane] : 0.0f;
        #pragma unroll
        for (int o = NWARPS / 2; o; o >>= 1) v += __shfl_xor_sync(0xffffffffu, v, o);
        if (lane == 0) g_partial[n] = (double)v;
    }

    // Completion ticket: last block to arrive does the final reduction.
    if (tid == 0) {
        __threadfence();
        unsigned int prev = atomicAdd(&g_done, 1u);
        s_is_last = (prev == (unsigned int)(gridDim.x - 1));
    }
    __syncthreads();

    if (s_is_last) {
        // Fixed-order deterministic reduction over N partials, in double.
        double d = 0.0;
        for (int i = tid; i < N; i += NWARPS * 32) {
            // L1 may be stale for other blocks' writes; read via L2.
            double val;
            asm volatile("ld.global.cg.f64 %0, [%1];"
                         : "=d"(val) : "l"(g_partial + i));
            d += val;
        }
        // block reduce (double): warp shuffles + smem
        #pragma unroll
        for (int o = 16; o; o >>= 1)
            d += __shfl_xor_sync(0xffffffffu, d, o);
        __shared__ double s_dsum[NWARPS];
        if (lane == 0) s_dsum[wid] = d;
        __syncthreads();
        if (wid == 0) {
            double t = (lane < NWARPS) ? s_dsum[lane] : 0.0;
            #pragma unroll
            for (int o = NWARPS / 2; o; o >>= 1)
                t += __shfl_xor_sync(0xffffffffu, t, o);
            if (lane == 0) {
                out[0] = (float)(-t / (double)N);
                g_done = 0u;                      // reset for next graph replay
            }
        }
    }
}

extern "C" void kernel_launch(void* const* d_in, const int* in_sizes, int n_in,
                              void* d_out, int out_size) {
    const float* input         = (const float*)d_in[0];
    const int*   target        = (const int*)  d_in[1];
    const int*   noise_samples = (const int*)  d_in[2];
    const float* noise         = (const float*)d_in[3];
    const float* weight        = (const float*)d_in[4];
    const float* bias          = (const float*)d_in[5];
    float* out = (float*)d_out;

    const int N = in_sizes[1];  // target element count

    nce_loss_kernel<<<N, NWARPS * 32>>>(input, target, noise_samples, noise,
                                        weight, bias, out, N);
}